// round 12
// baseline (speedup 1.0000x reference)
#include <cuda_runtime.h>
#include <math.h>

// Problem constants
#define BB   8
#define NN   4096
#define CC   512
#define HH   64
#define WW2  64
#define HEADS 16
#define HD   32

// ---------------- scratch (device globals; no cudaMalloc allowed) ----------------
__device__ float  g_qn[BB*CC*NN];          // q_nchw  [b][c][n]
__device__ float  g_kn[BB*CC*NN];          // k_nchw  [b][c][n]
__device__ float  g_qr[BB*HEADS*NN*HD];    // q_rope  [b][h][n][d]
__device__ float  g_kr[BB*HEADS*NN*HD];    // k_rope  [b][h][n][d]
__device__ double g_sqd[BB*NN];            // spatial gate q logits (fp64 accum)
__device__ double g_skd[BB*NN];
__device__ float  g_sq[BB*NN];             // sigmoid(s) fp32
__device__ float  g_sk[BB*NN];
__device__ float  g_pq[BB*CC];             // pooled
__device__ float  g_pk[BB*CC];
__device__ float  g_tq[BB*CC];             // channel gate
__device__ float  g_tk[BB*CC];
__device__ float  g_km[BB*HEADS*HD];       // k_mean
__device__ double g_kv[BB*HEADS*HD*HD];    // raw k^T v (fp64 accum, unscaled)

__device__ __forceinline__ float sigm(float x){ return 1.f/(1.f+expf(-x)); }

// ---------------- 1) qk projection GEMM: out = x @ qk_w^T + qk_b ----------------
// Near-exact: fp32 FFMA partial chains of 16 terms flushed into fp64 accumulators.
// M = B*N = 32768, K = 512, O = 1024. Writes transposed into g_qn / g_kn ([b][c][n]).
// Block 256 thr, tile 64(m) x 64(o), 4x4 per thread. Grid (512, 16).
__global__ __launch_bounds__(256) void k_gemm_qk(
    const float* __restrict__ x, const float* __restrict__ w, const float* __restrict__ bias)
{
    __shared__ float As[8][64];
    __shared__ float Bs[8][64];
    int t = threadIdx.x;
    int mBlk = blockIdx.x * 64;
    int oBlk = blockIdx.y * 64;
    int lr = t >> 2;            // 0..63
    int lc = (t & 3) * 2;       // 0,2,4,6
    const float* xg = x + (size_t)(mBlk + lr) * CC + lc;
    const float* wg = w + (size_t)(oBlk + lr) * CC + lc;
    int ty = t & 15;            // m direction (16 x 4 = 64)
    int tx = t >> 4;            // o direction (16 x 4 = 64)

    float  facc[4][4];
    double dacc[4][4];
    #pragma unroll
    for (int i = 0; i < 4; i++)
        #pragma unroll
        for (int j = 0; j < 4; j++) { facc[i][j] = 0.f; dacc[i][j] = 0.0; }

    for (int k0 = 0; k0 < CC; k0 += 8) {
        float2 a  = *(const float2*)(xg + k0);
        float2 bv = *(const float2*)(wg + k0);
        __syncthreads();
        As[lc  ][lr] = a.x;  As[lc+1][lr] = a.y;
        Bs[lc  ][lr] = bv.x; Bs[lc+1][lr] = bv.y;
        __syncthreads();
        #pragma unroll
        for (int kk = 0; kk < 8; kk++) {
            float4 av = *(const float4*)&As[kk][ty*4];
            float4 bw = *(const float4*)&Bs[kk][tx*4];
            float ra[4] = {av.x, av.y, av.z, av.w};
            float rb[4] = {bw.x, bw.y, bw.z, bw.w};
            #pragma unroll
            for (int i = 0; i < 4; i++)
                #pragma unroll
                for (int j = 0; j < 4; j++)
                    facc[i][j] += ra[i] * rb[j];
        }
        if (k0 & 8) {       // flush every 2nd k-block: fp32 chains of 16 terms
            #pragma unroll
            for (int i = 0; i < 4; i++)
                #pragma unroll
                for (int j = 0; j < 4; j++) {
                    dacc[i][j] += (double)facc[i][j];
                    facc[i][j] = 0.f;
                }
        }
    }
    int b  = mBlk >> 12;          // 4096 rows per batch, mBlk multiple of 64
    int n0 = mBlk & 4095;
    #pragma unroll
    for (int j = 0; j < 4; j++) {
        int o = oBlk + tx*4 + j;
        float bb = bias[o];
        float* dst = (o < CC) ? g_qn : g_kn;
        int oc = o & (CC - 1);
        size_t base = ((size_t)b*CC + oc) * NN + n0 + ty*4;
        float4 v;
        v.x = __fadd_rn((float)dacc[0][j], bb);
        v.y = __fadd_rn((float)dacc[1][j], bb);
        v.z = __fadd_rn((float)dacc[2][j], bb);
        v.w = __fadd_rn((float)dacc[3][j], bb);
        *(float4*)(dst + base) = v;
    }
}

// ------------- 2) spatial gate logits: dwconv3x3 + BN + relu, dot with pw_w -------------
// Products pre-rounded to fp32 (XLA multiply-then-reduce fusion), accumulated fp64.
// grid: b(8) x hwtile(16) x cchunk(8) = 1024 blocks, 256 threads (one hw position each).
__global__ __launch_bounds__(256) void k_spatial(
    const float* __restrict__ inp, const float* __restrict__ dw_w,
    const float* __restrict__ dw_b, const float* __restrict__ bn_g,
    const float* __restrict__ bn_b, const float* __restrict__ pw_w,
    double* __restrict__ s_raw)
{
    int bx = blockIdx.x;
    int cch  = bx & 7;
    int tile = (bx >> 3) & 15;
    int b    = bx >> 7;
    int t = threadIdx.x;
    int pos = tile*256 + t;
    int h = pos >> 6, w = pos & 63;
    const float bnc = (float)(1.0/sqrt(1.0 + 1e-5));   // compile-time double, correctly rounded
    double acc = 0.0;
    int c0 = cch * 64;
    for (int c = c0; c < c0 + 64; c++) {
        const float* p  = inp + ((size_t)b*CC + c) * NN;
        const float* wd = dw_w + c*9;
        float conv = 0.f;
        #pragma unroll
        for (int dy = -1; dy <= 1; dy++) {
            int hh = h + dy;
            if (hh < 0 || hh > 63) continue;
            #pragma unroll
            for (int dx = -1; dx <= 1; dx++) {
                int wp = w + dx;
                if (wp < 0 || wp > 63) continue;
                conv += p[hh*64 + wp] * wd[(dy+1)*3 + (dx+1)];
            }
        }
        // BN: separate mul then add (XLA elementwise, no FMA fusion)
        float y = __fadd_rn(__fmul_rn(__fadd_rn(conv, dw_b[c]), __fmul_rn(bn_g[c], bnc)), bn_b[c]);
        y = fmaxf(y, 0.f);
        float prod = __fmul_rn(y, pw_w[c]);   // fp32-rounded product, then fp64 reduce
        acc += (double)prod;
    }
    atomicAdd(&s_raw[b*NN + pos], acc);
}

// ------------- 2b) sigmoid over the gate logits (double -> float) -------------
__global__ __launch_bounds__(512) void k_sig(const double* __restrict__ a, float* __restrict__ o)
{
    int i = blockIdx.x * 512 + threadIdx.x;
    o[i] = sigm((float)a[i]);
}

// ------------- 3) pooled = mean_hw( nchw * s ) : fp32 products, fp64 reduce -------------
__global__ __launch_bounds__(256) void k_pool(
    const float* __restrict__ inp, const float* __restrict__ s,
    float* __restrict__ pool)
{
    int bc = blockIdx.x;            // b*512 + c
    int b  = bc >> 9;
    const float* p  = inp + (size_t)bc * NN;
    const float* sp = s + b*NN;
    int t = threadIdx.x;
    double sum = 0.0;
    for (int j = t; j < NN; j += 256) {
        float prod = __fmul_rn(p[j], sp[j]);   // materialized x*s in fp32 (reference rounds here)
        sum += (double)prod;
    }
    __shared__ double red[256];
    red[t] = sum; __syncthreads();
    for (int st = 128; st > 0; st >>= 1) {
        if (t < st) red[t] += red[t + st];
        __syncthreads();
    }
    if (t == 0) pool[bc] = __fmul_rn((float)red[0], 1.f / NN);
}

// ------------- 4) channel gate: t[b][o] = sigmoid( sum_c w[o,c] pool[b,c] ), fp64 dot -------------
__global__ __launch_bounds__(512) void k_chgate(
    const float* __restrict__ w, const float* __restrict__ pool,
    float* __restrict__ tg)
{
    int b = blockIdx.x;
    int o = threadIdx.x;
    __shared__ float ps[CC];
    ps[o] = pool[b*CC + o];
    __syncthreads();
    const float* wr = w + (size_t)o * CC;
    double dot = 0.0;
    #pragma unroll 4
    for (int c = 0; c < CC; c += 4) {
        float4 wv = *(const float4*)(wr + c);
        dot += (double)wv.x*ps[c] + (double)wv.y*ps[c+1] + (double)wv.z*ps[c+2] + (double)wv.w*ps[c+3];
    }
    tg[b*CC + o] = sigm((float)dot);
}

// ------------- 5) apply gates + elu+1 (expm1, JAX) + RoPE (no FMA fusion), write [b][h][n][d] -------------
// grid: b(8) x head(16) x nchunk(256); block 256 = 16 i_local x 16 n_local
__global__ __launch_bounds__(256) void k_rope(
    const float* __restrict__ inp, const float* __restrict__ s,
    const float* __restrict__ tg, const float* __restrict__ cosT,
    const float* __restrict__ sinT, float* __restrict__ outr)
{
    int bx = blockIdx.x;
    int nc   = bx & 255;
    int head = (bx >> 8) & 15;
    int b    = bx >> 12;
    int t = threadIdx.x;
    int n_l = t & 15;
    int i_l = t >> 4;
    int n = nc*16 + n_l;
    int ig = head*16 + i_l;
    int c0 = 2*ig;
    float sg = s[b*NN + n];
    float v0 = __fmul_rn(__fmul_rn(inp[((size_t)b*CC + c0    )*NN + n], sg), tg[b*CC + c0]);
    float v1 = __fmul_rn(__fmul_rn(inp[((size_t)b*CC + c0 + 1)*NN + n], sg), tg[b*CC + c0 + 1]);
    v0 = (v0 > 0.f) ? __fadd_rn(v0, 1.f) : __fadd_rn(expm1f(v0), 1.f);   // elu(x)+1
    v1 = (v1 > 0.f) ? __fadd_rn(v1, 1.f) : __fadd_rn(expm1f(v1), 1.f);
    float cs = cosT[n*256 + ig], sn = sinT[n*256 + ig];
    float re = __fsub_rn(__fmul_rn(cs, v0), __fmul_rn(sn, v1));   // mul;mul;sub — XLA rounding
    float im = __fadd_rn(__fmul_rn(sn, v0), __fmul_rn(cs, v1));
    __shared__ float tile[16*32];
    tile[n_l*32 + 2*i_l    ] = re;
    tile[n_l*32 + 2*i_l + 1] = im;
    __syncthreads();
    size_t base = (((size_t)b*HEADS + head)*NN + (size_t)nc*16) * HD;
    outr[base + t]       = tile[t];
    outr[base + 256 + t] = tile[256 + t];
}

// ------------- 6) k_mean over n : fp64 accumulation -------------
__global__ __launch_bounds__(256) void k_kmean(const float* __restrict__ kr, float* __restrict__ km)
{
    int bh = blockIdx.x;            // 0..127
    int t = threadIdx.x;
    int d = t & 31, ch = t >> 5;
    const float* p = kr + (size_t)bh * NN * HD;
    double sum = 0.0;
    int j0 = ch * 512;
    for (int j = j0; j < j0 + 512; j++)
        sum += (double)p[(size_t)j*HD + d];
    __shared__ double red[256];
    red[t] = sum; __syncthreads();
    if (t < 32) {
        double s2 = 0.0;
        #pragma unroll
        for (int k = 0; k < 8; k++) s2 += red[k*32 + d];
        km[bh*HD + d] = __fmul_rn((float)s2, 1.f / NN);
    }
}

// ------------- 7) kv = sum_n k_rope[n,d] * v[n,e] : exact products, fp64 accum -------------
// grid: bh(128) x nchunk(8) = 1024 blocks, 256 threads
__global__ __launch_bounds__(256) void k_kv(
    const float* __restrict__ kr, const float* __restrict__ x, double* __restrict__ kv)
{
    int bx = blockIdx.x;
    int nch = bx & 7;
    int bh  = bx >> 3;
    int b = bh >> 4, h = bh & 15;
    int t = threadIdx.x;
    int d  = t & 31;
    int e0 = (t >> 5) * 4;
    __shared__ float ks[64*32];
    __shared__ float vs[64*32];
    double a0 = 0.0, a1 = 0.0, a2 = 0.0, a3 = 0.0;
    for (int sub = 0; sub < 8; sub++) {
        int nbase = nch*512 + sub*64;
        const float4* src = (const float4*)(kr + ((size_t)bh*NN + nbase) * HD);
        ((float4*)ks)[t]       = src[t];
        ((float4*)ks)[t + 256] = src[t + 256];
        #pragma unroll
        for (int r = 0; r < 2; r++) {
            int id = t + r*256;
            int nn = id >> 3, e4 = (id & 7) * 4;
            float4 vv = *(const float4*)(x + ((size_t)b*NN + nbase + nn)*CC + h*HD + e4);
            *(float4*)&vs[nn*32 + e4] = vv;
        }
        __syncthreads();
        #pragma unroll 8
        for (int nn2 = 0; nn2 < 64; nn2++) {
            double kd = (double)ks[nn2*32 + d];
            a0 += kd * vs[nn2*32 + e0];
            a1 += kd * vs[nn2*32 + e0 + 1];
            a2 += kd * vs[nn2*32 + e0 + 2];
            a3 += kd * vs[nn2*32 + e0 + 3];
        }
        __syncthreads();
    }
    double* dst = kv + ((size_t)bh*HD + d) * HD + e0;
    atomicAdd(dst + 0, a0); atomicAdd(dst + 1, a1);
    atomicAdd(dst + 2, a2); atomicAdd(dst + 3, a3);
}

// ------------- 8) epilogue: z (fp64 dot, exact), q.kv (fp32 ascending), lepe (fp32), sum -------------
// grid: b*n = 32768 blocks, 512 threads (one c each)
__global__ __launch_bounds__(512) void k_final(
    const float* __restrict__ x, const float* __restrict__ qr,
    const float* __restrict__ km, const double* __restrict__ kv,
    const float* __restrict__ lw, const float* __restrict__ lb,
    float* __restrict__ out)
{
    int bx = blockIdx.x;
    int b = bx >> 12;
    int n = bx & 4095;
    int h = n >> 6, w = n & 63;
    int c = threadIdx.x;
    int head = c >> 5, e = c & 31;
    __shared__ float qs[CC];
    __shared__ float zs[HEADS];
    __shared__ float lws[CC*9];
    qs[c] = qr[(((size_t)b*HEADS + head)*NN + n)*HD + e];
    #pragma unroll
    for (int k = 0; k < 9; k++) lws[k*CC + c] = lw[k*CC + c];
    __syncthreads();
    if (c < HEADS) {
        // z-dot: fp64-exact on my side; ref noise is the irreducible floor
        const float* kmp = km + ((size_t)b*HEADS + c) * HD;
        double dz = 0.0;
        #pragma unroll
        for (int d2 = 0; d2 < HD; d2++) dz += (double)qs[c*HD + d2] * (double)kmp[d2];
        zs[c] = 1.f / __fadd_rn((float)dz, 1e-6f);
    }
    __syncthreads();
    // out-dot: fp32 ascending-d FMA chain; kv materialized to fp32 then /4096 (exact pow2)
    const double* kvp = kv + ((size_t)b*HEADS + head) * HD * HD + e;
    float dd = 0.f;
    #pragma unroll
    for (int d2 = 0; d2 < HD; d2++) {
        float kvf = __fmul_rn((float)kvp[d2*HD], 1.f / NN);
        dd += qs[head*HD + d2] * kvf;
    }
    float lep = lb[c];
    #pragma unroll
    for (int dy = -1; dy <= 1; dy++) {
        int hh = h + dy;
        if (hh < 0 || hh > 63) continue;
        #pragma unroll
        for (int dx = -1; dx <= 1; dx++) {
            int wp = w + dx;
            if (wp < 0 || wp > 63) continue;
            int nn = hh*64 + wp;
            lep += x[((size_t)b*NN + nn)*CC + c] * lws[c*9 + (dy+1)*3 + (dx+1)];
        }
    }
    // out = (dd*z) + lepe : separate mul then add (two fp32 tensors added in reference)
    out[((size_t)b*NN + n)*CC + c] = __fadd_rn(__fmul_rn(dd, zs[head]), lep);
}

// ---------------- launch ----------------
extern "C" void kernel_launch(void* const* d_in, const int* in_sizes, int n_in,
                              void* d_out, int out_size)
{
    const float* x        = (const float*)d_in[0];
    const float* qk_w     = (const float*)d_in[1];
    const float* qk_b     = (const float*)d_in[2];
    const float* qsp_dw_w = (const float*)d_in[3];
    const float* qsp_dw_b = (const float*)d_in[4];
    const float* qsp_bn_g = (const float*)d_in[5];
    const float* qsp_bn_b = (const float*)d_in[6];
    const float* qsp_pw_w = (const float*)d_in[7];
    const float* qch_w    = (const float*)d_in[8];
    const float* ksp_dw_w = (const float*)d_in[9];
    const float* ksp_dw_b = (const float*)d_in[10];
    const float* ksp_bn_g = (const float*)d_in[11];
    const float* ksp_bn_b = (const float*)d_in[12];
    const float* ksp_pw_w = (const float*)d_in[13];
    const float* kch_w    = (const float*)d_in[14];
    const float* lepe_w   = (const float*)d_in[15];
    const float* lepe_b   = (const float*)d_in[16];
    const float* rope_cos = (const float*)d_in[17];
    const float* rope_sin = (const float*)d_in[18];

    float  *p_qn, *p_kn, *p_qr, *p_kr, *p_sq, *p_sk, *p_pq, *p_pk, *p_tq, *p_tk, *p_km;
    double *p_sqd, *p_skd, *p_kv;
    cudaGetSymbolAddress((void**)&p_qn, g_qn);
    cudaGetSymbolAddress((void**)&p_kn, g_kn);
    cudaGetSymbolAddress((void**)&p_qr, g_qr);
    cudaGetSymbolAddress((void**)&p_kr, g_kr);
    cudaGetSymbolAddress((void**)&p_sqd, g_sqd);
    cudaGetSymbolAddress((void**)&p_skd, g_skd);
    cudaGetSymbolAddress((void**)&p_sq, g_sq);
    cudaGetSymbolAddress((void**)&p_sk, g_sk);
    cudaGetSymbolAddress((void**)&p_pq, g_pq);
    cudaGetSymbolAddress((void**)&p_pk, g_pk);
    cudaGetSymbolAddress((void**)&p_tq, g_tq);
    cudaGetSymbolAddress((void**)&p_tk, g_tk);
    cudaGetSymbolAddress((void**)&p_km, g_km);
    cudaGetSymbolAddress((void**)&p_kv, g_kv);

    cudaMemsetAsync(p_sqd, 0, BB*NN*sizeof(double));
    cudaMemsetAsync(p_skd, 0, BB*NN*sizeof(double));
    cudaMemsetAsync(p_kv, 0, BB*HEADS*HD*HD*sizeof(double));

    dim3 gg(512, 16);
    k_gemm_qk<<<gg, 256>>>(x, qk_w, qk_b);

    k_spatial<<<1024, 256>>>(p_qn, qsp_dw_w, qsp_dw_b, qsp_bn_g, qsp_bn_b, qsp_pw_w, p_sqd);
    k_spatial<<<1024, 256>>>(p_kn, ksp_dw_w, ksp_dw_b, ksp_bn_g, ksp_bn_b, ksp_pw_w, p_skd);
    k_sig<<<64, 512>>>(p_sqd, p_sq);
    k_sig<<<64, 512>>>(p_skd, p_sk);

    k_pool<<<4096, 256>>>(p_qn, p_sq, p_pq);
    k_pool<<<4096, 256>>>(p_kn, p_sk, p_pk);
    k_chgate<<<8, 512>>>(qch_w, p_pq, p_tq);
    k_chgate<<<8, 512>>>(kch_w, p_pk, p_tk);

    k_rope<<<32768, 256>>>(p_qn, p_sq, p_tq, rope_cos, rope_sin, p_qr);
    k_rope<<<32768, 256>>>(p_kn, p_sk, p_tk, rope_cos, rope_sin, p_kr);

    k_kmean<<<128, 256>>>(p_kr, p_km);
    k_kv<<<1024, 256>>>(p_kr, x, p_kv);

    k_final<<<32768, 512>>>(x, p_qr, p_km, p_kv, lepe_w, lepe_b, (float*)d_out);
}

// round 14
// speedup vs baseline: 3.9849x; 3.9849x over previous
#include <cuda_runtime.h>
#include <math.h>

// Problem constants
#define BB   8
#define NN   4096
#define CC   512
#define HH   64
#define WW2  64
#define HEADS 16
#define HD   32

// ---------------- scratch (device globals; no cudaMalloc allowed) ----------------
__device__ float  g_qn[BB*CC*NN];          // q_nchw  [b][c][n]
__device__ float  g_kn[BB*CC*NN];          // k_nchw  [b][c][n]
__device__ float  g_qr[BB*HEADS*NN*HD];    // q_rope  [b][h][n][d]
__device__ float  g_kr[BB*HEADS*NN*HD];    // k_rope  [b][h][n][d]
__device__ double g_sqd[BB*NN];            // spatial gate q logits (fp64 accum)
__device__ double g_skd[BB*NN];
__device__ float  g_sq[BB*NN];             // sigmoid(s) fp32
__device__ float  g_sk[BB*NN];
__device__ float  g_pq[BB*CC];             // pooled
__device__ float  g_pk[BB*CC];
__device__ float  g_tq[BB*CC];             // channel gate
__device__ float  g_tk[BB*CC];
__device__ float  g_km[BB*HEADS*HD];       // k_mean
__device__ float  g_kv[BB*HEADS*HD*HD];    // raw k^T v (fp32, unscaled)

__device__ __forceinline__ float sigm(float x){ return 1.f/(1.f+expf(-x)); }

// ---------------- 1) qk projection GEMM: out = x @ qk_w^T + qk_b ----------------
// Pure fp32, SERIAL k-ascending FFMA chain per output (bit-matches cuBLAS SIMT sgemm).
// M = B*N = 32768, K = 512, O = 1024. Writes transposed into g_qn / g_kn ([b][c][n]).
// Block 256 thr, tile 128(m) x 128(o), 8x8 per thread. Grid (256, 8).
__global__ __launch_bounds__(256) void k_gemm_qk(
    const float* __restrict__ x, const float* __restrict__ w, const float* __restrict__ bias)
{
    __shared__ float As[8][128];
    __shared__ float Bs[8][128];
    int t = threadIdx.x;
    int mBlk = blockIdx.x * 128;
    int oBlk = blockIdx.y * 128;
    int lr = t >> 1;
    int lc = (t & 1) * 4;
    const float* xg = x + (size_t)(mBlk + lr) * CC + lc;
    const float* wg = w + (size_t)(oBlk + lr) * CC + lc;
    int ty = t & 15;      // m direction
    int tx = t >> 4;      // o direction
    float acc[8][8];
    #pragma unroll
    for (int i = 0; i < 8; i++)
        #pragma unroll
        for (int j = 0; j < 8; j++) acc[i][j] = 0.f;

    // register prefetch double-buffering
    float4 a  = *(const float4*)(xg);
    float4 bv = *(const float4*)(wg);

    for (int k0 = 0; k0 < CC; k0 += 8) {
        __syncthreads();
        As[lc  ][lr] = a.x;  As[lc+1][lr] = a.y;  As[lc+2][lr] = a.z;  As[lc+3][lr] = a.w;
        Bs[lc  ][lr] = bv.x; Bs[lc+1][lr] = bv.y; Bs[lc+2][lr] = bv.z; Bs[lc+3][lr] = bv.w;
        __syncthreads();
        if (k0 + 8 < CC) {
            a  = *(const float4*)(xg + k0 + 8);
            bv = *(const float4*)(wg + k0 + 8);
        }
        #pragma unroll
        for (int kk = 0; kk < 8; kk++) {
            float4 a0 = *(const float4*)&As[kk][ty*4];
            float4 a1 = *(const float4*)&As[kk][64 + ty*4];
            float4 b0 = *(const float4*)&Bs[kk][tx*4];
            float4 b1 = *(const float4*)&Bs[kk][64 + tx*4];
            float ra[8] = {a0.x,a0.y,a0.z,a0.w,a1.x,a1.y,a1.z,a1.w};
            float rb[8] = {b0.x,b0.y,b0.z,b0.w,b1.x,b1.y,b1.z,b1.w};
            #pragma unroll
            for (int i = 0; i < 8; i++)
                #pragma unroll
                for (int j = 0; j < 8; j++)
                    acc[i][j] += ra[i] * rb[j];     // serial over k, strict order
        }
    }
    int b  = mBlk >> 12;          // 4096 rows per batch, mBlk multiple of 128
    int n0 = mBlk & 4095;
    #pragma unroll
    for (int j = 0; j < 8; j++) {
        int o = oBlk + ((j < 4) ? tx*4 + j : 64 + tx*4 + (j - 4));
        float bb = bias[o];
        float* dst = (o < CC) ? g_qn : g_kn;
        int oc = o & (CC - 1);
        size_t base = ((size_t)b*CC + oc) * NN + n0;
        #pragma unroll
        for (int g = 0; g < 2; g++) {
            int m0 = g*64 + ty*4;
            float4 v;
            v.x = __fadd_rn(acc[g*4+0][j], bb);
            v.y = __fadd_rn(acc[g*4+1][j], bb);
            v.z = __fadd_rn(acc[g*4+2][j], bb);
            v.w = __fadd_rn(acc[g*4+3][j], bb);
            *(float4*)(dst + base + m0) = v;
        }
    }
}

// ------------- 2) spatial gate logits: dwconv3x3 + BN + relu, dot with pw_w -------------
// Products pre-rounded to fp32 (XLA multiply-then-reduce fusion), accumulated fp64.
// grid: b(8) x hwtile(16) x cchunk(8) = 1024 blocks, 256 threads (one hw position each).
__global__ __launch_bounds__(256) void k_spatial(
    const float* __restrict__ inp, const float* __restrict__ dw_w,
    const float* __restrict__ dw_b, const float* __restrict__ bn_g,
    const float* __restrict__ bn_b, const float* __restrict__ pw_w,
    double* __restrict__ s_raw)
{
    int bx = blockIdx.x;
    int cch  = bx & 7;
    int tile = (bx >> 3) & 15;
    int b    = bx >> 7;
    int t = threadIdx.x;
    int pos = tile*256 + t;
    int h = pos >> 6, w = pos & 63;
    const float bnc = (float)(1.0/sqrt(1.0 + 1e-5));
    double acc = 0.0;
    int c0 = cch * 64;
    for (int c = c0; c < c0 + 64; c++) {
        const float* p  = inp + ((size_t)b*CC + c) * NN;
        const float* wd = dw_w + c*9;
        float conv = 0.f;
        #pragma unroll
        for (int dy = -1; dy <= 1; dy++) {
            int hh = h + dy;
            if (hh < 0 || hh > 63) continue;
            #pragma unroll
            for (int dx = -1; dx <= 1; dx++) {
                int wp = w + dx;
                if (wp < 0 || wp > 63) continue;
                conv += p[hh*64 + wp] * wd[(dy+1)*3 + (dx+1)];
            }
        }
        float y = __fadd_rn(__fmul_rn(__fadd_rn(conv, dw_b[c]), __fmul_rn(bn_g[c], bnc)), bn_b[c]);
        y = fmaxf(y, 0.f);
        float prod = __fmul_rn(y, pw_w[c]);
        acc += (double)prod;
    }
    atomicAdd(&s_raw[b*NN + pos], acc);
}

// ------------- 2b) sigmoid over the gate logits (double -> float) -------------
__global__ __launch_bounds__(512) void k_sig(const double* __restrict__ a, float* __restrict__ o)
{
    int i = blockIdx.x * 512 + threadIdx.x;
    o[i] = sigm((float)a[i]);
}

// ------------- 3) pooled = mean_hw( nchw * s ) : fp32 products, fp64 reduce -------------
__global__ __launch_bounds__(256) void k_pool(
    const float* __restrict__ inp, const float* __restrict__ s,
    float* __restrict__ pool)
{
    int bc = blockIdx.x;            // b*512 + c
    int b  = bc >> 9;
    const float* p  = inp + (size_t)bc * NN;
    const float* sp = s + b*NN;
    int t = threadIdx.x;
    double sum = 0.0;
    for (int j = t; j < NN; j += 256) {
        float prod = __fmul_rn(p[j], sp[j]);
        sum += (double)prod;
    }
    __shared__ double red[256];
    red[t] = sum; __syncthreads();
    for (int st = 128; st > 0; st >>= 1) {
        if (t < st) red[t] += red[t + st];
        __syncthreads();
    }
    if (t == 0) pool[bc] = __fmul_rn((float)red[0], 1.f / NN);
}

// ------------- 4) channel gate: t[b][o] = sigmoid( sum_c w[o,c] pool[b,c] ), fp64 dot -------------
__global__ __launch_bounds__(512) void k_chgate(
    const float* __restrict__ w, const float* __restrict__ pool,
    float* __restrict__ tg)
{
    int b = blockIdx.x;
    int o = threadIdx.x;
    __shared__ float ps[CC];
    ps[o] = pool[b*CC + o];
    __syncthreads();
    const float* wr = w + (size_t)o * CC;
    double dot = 0.0;
    #pragma unroll 4
    for (int c = 0; c < CC; c += 4) {
        float4 wv = *(const float4*)(wr + c);
        dot += (double)wv.x*ps[c] + (double)wv.y*ps[c+1] + (double)wv.z*ps[c+2] + (double)wv.w*ps[c+3];
    }
    tg[b*CC + o] = sigm((float)dot);
}

// ------------- 5) apply gates + elu+1 (expm1, JAX) + RoPE (no FMA fusion), write [b][h][n][d] -------------
// grid: b(8) x head(16) x nchunk(256); block 256 = 16 i_local x 16 n_local
__global__ __launch_bounds__(256) void k_rope(
    const float* __restrict__ inp, const float* __restrict__ s,
    const float* __restrict__ tg, const float* __restrict__ cosT,
    const float* __restrict__ sinT, float* __restrict__ outr)
{
    int bx = blockIdx.x;
    int nc   = bx & 255;
    int head = (bx >> 8) & 15;
    int b    = bx >> 12;
    int t = threadIdx.x;
    int n_l = t & 15;
    int i_l = t >> 4;
    int n = nc*16 + n_l;
    int ig = head*16 + i_l;
    int c0 = 2*ig;
    float sg = s[b*NN + n];
    float v0 = __fmul_rn(__fmul_rn(inp[((size_t)b*CC + c0    )*NN + n], sg), tg[b*CC + c0]);
    float v1 = __fmul_rn(__fmul_rn(inp[((size_t)b*CC + c0 + 1)*NN + n], sg), tg[b*CC + c0 + 1]);
    v0 = (v0 > 0.f) ? __fadd_rn(v0, 1.f) : __fadd_rn(expm1f(v0), 1.f);   // elu(x)+1
    v1 = (v1 > 0.f) ? __fadd_rn(v1, 1.f) : __fadd_rn(expm1f(v1), 1.f);
    float cs = cosT[n*256 + ig], sn = sinT[n*256 + ig];
    float re = __fsub_rn(__fmul_rn(cs, v0), __fmul_rn(sn, v1));   // mul;mul;sub — XLA rounding
    float im = __fadd_rn(__fmul_rn(sn, v0), __fmul_rn(cs, v1));
    __shared__ float tile[16*32];
    tile[n_l*32 + 2*i_l    ] = re;
    tile[n_l*32 + 2*i_l + 1] = im;
    __syncthreads();
    size_t base = (((size_t)b*HEADS + head)*NN + (size_t)nc*16) * HD;
    outr[base + t]       = tile[t];
    outr[base + 256 + t] = tile[256 + t];
}

// ------------- 6) k_mean over n : fp64 accumulation (z-amplified path, keep exact) -------------
__global__ __launch_bounds__(256) void k_kmean(const float* __restrict__ kr, float* __restrict__ km)
{
    int bh = blockIdx.x;            // 0..127
    int t = threadIdx.x;
    int d = t & 31, ch = t >> 5;
    const float* p = kr + (size_t)bh * NN * HD;
    double sum = 0.0;
    int j0 = ch * 512;
    for (int j = j0; j < j0 + 512; j++)
        sum += (double)p[(size_t)j*HD + d];
    __shared__ double red[256];
    red[t] = sum; __syncthreads();
    if (t < 32) {
        double s2 = 0.0;
        #pragma unroll
        for (int k = 0; k < 8; k++) s2 += red[k*32 + d];
        km[bh*HD + d] = __fmul_rn((float)s2, 1.f / NN);
    }
}

// ------------- 7) kv = sum_n k_rope[n,d] * v[n,e] : fp32 (not z-amplified; noise ~1e-6) -------------
// grid: bh(128) x nchunk(8) = 1024 blocks, 256 threads
__global__ __launch_bounds__(256) void k_kv(
    const float* __restrict__ kr, const float* __restrict__ x, float* __restrict__ kv)
{
    int bx = blockIdx.x;
    int nch = bx & 7;
    int bh  = bx >> 3;
    int b = bh >> 4, h = bh & 15;
    int t = threadIdx.x;
    int d  = t & 31;
    int e0 = (t >> 5) * 4;
    __shared__ float ks[64*32];
    __shared__ float vs[64*32];
    float a0 = 0.f, a1 = 0.f, a2 = 0.f, a3 = 0.f;
    for (int sub = 0; sub < 8; sub++) {
        int nbase = nch*512 + sub*64;
        const float4* src = (const float4*)(kr + ((size_t)bh*NN + nbase) * HD);
        ((float4*)ks)[t]       = src[t];
        ((float4*)ks)[t + 256] = src[t + 256];
        #pragma unroll
        for (int r = 0; r < 2; r++) {
            int id = t + r*256;
            int nn = id >> 3, e4 = (id & 7) * 4;
            float4 vv = *(const float4*)(x + ((size_t)b*NN + nbase + nn)*CC + h*HD + e4);
            *(float4*)&vs[nn*32 + e4] = vv;
        }
        __syncthreads();
        #pragma unroll 8
        for (int nn2 = 0; nn2 < 64; nn2++) {
            float kd = ks[nn2*32 + d];
            a0 += kd * vs[nn2*32 + e0];
            a1 += kd * vs[nn2*32 + e0 + 1];
            a2 += kd * vs[nn2*32 + e0 + 2];
            a3 += kd * vs[nn2*32 + e0 + 3];
        }
        __syncthreads();
    }
    float* dst = kv + ((size_t)bh*HD + d) * HD + e0;
    atomicAdd(dst + 0, a0); atomicAdd(dst + 1, a1);
    atomicAdd(dst + 2, a2); atomicAdd(dst + 3, a3);
}

// ------------- 8) epilogue: z (fp64 dot), q.kv (fp32 ascending), lepe (fp32), sum -------------
// grid: b*n = 32768 blocks, 512 threads (one c each)
__global__ __launch_bounds__(512) void k_final(
    const float* __restrict__ x, const float* __restrict__ qr,
    const float* __restrict__ km, const float* __restrict__ kv,
    const float* __restrict__ lw, const float* __restrict__ lb,
    float* __restrict__ out)
{
    int bx = blockIdx.x;
    int b = bx >> 12;
    int n = bx & 4095;
    int h = n >> 6, w = n & 63;
    int c = threadIdx.x;
    int head = c >> 5, e = c & 31;
    __shared__ float qs[CC];
    __shared__ float zs[HEADS];
    __shared__ float lws[CC*9];
    qs[c] = qr[(((size_t)b*HEADS + head)*NN + n)*HD + e];
    #pragma unroll
    for (int k = 0; k < 9; k++) lws[k*CC + c] = lw[k*CC + c];
    __syncthreads();
    if (c < HEADS) {
        // z-dot: fp64 (z-amplified denominator — keep exact on my side)
        const float* kmp = km + ((size_t)b*HEADS + c) * HD;
        double dz = 0.0;
        #pragma unroll
        for (int d2 = 0; d2 < HD; d2++) dz += (double)qs[c*HD + d2] * (double)kmp[d2];
        zs[c] = 1.f / __fadd_rn((float)dz, 1e-6f);
    }
    __syncthreads();
    // out-dot: fp32 ascending-d FMA chain; kv/4096 (exact pow2 scale)
    const float* kvp = kv + ((size_t)b*HEADS + head) * HD * HD + e;
    float dd = 0.f;
    #pragma unroll
    for (int d2 = 0; d2 < HD; d2++) {
        float kvf = __fmul_rn(kvp[d2*HD], 1.f / NN);
        dd += qs[head*HD + d2] * kvf;
    }
    float lep = lb[c];
    #pragma unroll
    for (int dy = -1; dy <= 1; dy++) {
        int hh = h + dy;
        if (hh < 0 || hh > 63) continue;
        #pragma unroll
        for (int dx = -1; dx <= 1; dx++) {
            int wp = w + dx;
            if (wp < 0 || wp > 63) continue;
            int nn = hh*64 + wp;
            lep += x[((size_t)b*NN + nn)*CC + c] * lws[c*9 + (dy+1)*3 + (dx+1)];
        }
    }
    out[((size_t)b*NN + n)*CC + c] = __fadd_rn(__fmul_rn(dd, zs[head]), lep);
}

// ---------------- launch ----------------
extern "C" void kernel_launch(void* const* d_in, const int* in_sizes, int n_in,
                              void* d_out, int out_size)
{
    const float* x        = (const float*)d_in[0];
    const float* qk_w     = (const float*)d_in[1];
    const float* qk_b     = (const float*)d_in[2];
    const float* qsp_dw_w = (const float*)d_in[3];
    const float* qsp_dw_b = (const float*)d_in[4];
    const float* qsp_bn_g = (const float*)d_in[5];
    const float* qsp_bn_b = (const float*)d_in[6];
    const float* qsp_pw_w = (const float*)d_in[7];
    const float* qch_w    = (const float*)d_in[8];
    const float* ksp_dw_w = (const float*)d_in[9];
    const float* ksp_dw_b = (const float*)d_in[10];
    const float* ksp_bn_g = (const float*)d_in[11];
    const float* ksp_bn_b = (const float*)d_in[12];
    const float* ksp_pw_w = (const float*)d_in[13];
    const float* kch_w    = (const float*)d_in[14];
    const float* lepe_w   = (const float*)d_in[15];
    const float* lepe_b   = (const float*)d_in[16];
    const float* rope_cos = (const float*)d_in[17];
    const float* rope_sin = (const float*)d_in[18];

    float  *p_qn, *p_kn, *p_qr, *p_kr, *p_sq, *p_sk, *p_pq, *p_pk, *p_tq, *p_tk, *p_km, *p_kv;
    double *p_sqd, *p_skd;
    cudaGetSymbolAddress((void**)&p_qn, g_qn);
    cudaGetSymbolAddress((void**)&p_kn, g_kn);
    cudaGetSymbolAddress((void**)&p_qr, g_qr);
    cudaGetSymbolAddress((void**)&p_kr, g_kr);
    cudaGetSymbolAddress((void**)&p_sqd, g_sqd);
    cudaGetSymbolAddress((void**)&p_skd, g_skd);
    cudaGetSymbolAddress((void**)&p_sq, g_sq);
    cudaGetSymbolAddress((void**)&p_sk, g_sk);
    cudaGetSymbolAddress((void**)&p_pq, g_pq);
    cudaGetSymbolAddress((void**)&p_pk, g_pk);
    cudaGetSymbolAddress((void**)&p_tq, g_tq);
    cudaGetSymbolAddress((void**)&p_tk, g_tk);
    cudaGetSymbolAddress((void**)&p_km, g_km);
    cudaGetSymbolAddress((void**)&p_kv, g_kv);

    cudaMemsetAsync(p_sqd, 0, BB*NN*sizeof(double));
    cudaMemsetAsync(p_skd, 0, BB*NN*sizeof(double));
    cudaMemsetAsync(p_kv, 0, BB*HEADS*HD*HD*sizeof(float));

    dim3 gg(256, 8);
    k_gemm_qk<<<gg, 256>>>(x, qk_w, qk_b);

    k_spatial<<<1024, 256>>>(p_qn, qsp_dw_w, qsp_dw_b, qsp_bn_g, qsp_bn_b, qsp_pw_w, p_sqd);
    k_spatial<<<1024, 256>>>(p_kn, ksp_dw_w, ksp_dw_b, ksp_bn_g, ksp_bn_b, ksp_pw_w, p_skd);
    k_sig<<<64, 512>>>(p_sqd, p_sq);
    k_sig<<<64, 512>>>(p_skd, p_sk);

    k_pool<<<4096, 256>>>(p_qn, p_sq, p_pq);
    k_pool<<<4096, 256>>>(p_kn, p_sk, p_pk);
    k_chgate<<<8, 512>>>(qch_w, p_pq, p_tq);
    k_chgate<<<8, 512>>>(kch_w, p_pk, p_tk);

    k_rope<<<32768, 256>>>(p_qn, p_sq, p_tq, rope_cos, rope_sin, p_qr);
    k_rope<<<32768, 256>>>(p_kn, p_sk, p_tk, rope_cos, rope_sin, p_kr);

    k_kmean<<<128, 256>>>(p_kr, p_km);
    k_kv<<<1024, 256>>>(p_kr, x, p_kv);

    k_final<<<32768, 512>>>(x, p_qr, p_km, p_kv, lepe_w, lepe_b, (float*)d_out);
}

// round 16
// speedup vs baseline: 4.0115x; 1.0067x over previous
#include <cuda_runtime.h>
#include <math.h>

// Problem constants
#define BB   8
#define NN   4096
#define CC   512
#define HH   64
#define WW2  64
#define HEADS 16
#define HD   32

// ---------------- scratch (device globals; no cudaMalloc allowed) ----------------
__device__ float  g_qn[BB*CC*NN];          // q_nchw  [b][c][n]
__device__ float  g_kn[BB*CC*NN];          // k_nchw  [b][c][n]
__device__ float  g_qr[BB*HEADS*NN*HD];    // q_rope  [b][h][n][d]
__device__ float  g_kr[BB*HEADS*NN*HD];    // k_rope  [b][h][n][d]
__device__ double g_sqd[BB*NN];            // spatial gate q logits (fp64 accum)
__device__ double g_skd[BB*NN];
__device__ float  g_sq[BB*NN];             // sigmoid(s) fp32
__device__ float  g_sk[BB*NN];
__device__ float  g_pq[BB*CC];             // pooled
__device__ float  g_pk[BB*CC];
__device__ float  g_tq[BB*CC];             // channel gate
__device__ float  g_tk[BB*CC];
__device__ float  g_km[BB*HEADS*HD];       // k_mean
__device__ float  g_kv[BB*HEADS*HD*HD];    // raw k^T v (fp32, unscaled)

__device__ __forceinline__ float sigm(float x){ return 1.f/(1.f+expf(-x)); }

// ---------------- 1) qk projection GEMM: out = x @ qk_w^T + qk_b ----------------
// Pure fp32, SERIAL k-ascending FFMA chain per output (bit-matches cuBLAS SIMT sgemm;
// FFMA order identical to R14). Smem double-buffered: ONE barrier per k-block.
// Block 256 thr, tile 128(m) x 128(o), 8x8 per thread. Grid (256, 8).
__global__ __launch_bounds__(256) void k_gemm_qk(
    const float* __restrict__ x, const float* __restrict__ w, const float* __restrict__ bias)
{
    __shared__ float As[2][8][128];
    __shared__ float Bs[2][8][128];
    int t = threadIdx.x;
    int mBlk = blockIdx.x * 128;
    int oBlk = blockIdx.y * 128;
    int lr = t >> 1;
    int lc = (t & 1) * 4;
    const float* xg = x + (size_t)(mBlk + lr) * CC + lc;
    const float* wg = w + (size_t)(oBlk + lr) * CC + lc;
    int ty = t & 15;      // m direction
    int tx = t >> 4;      // o direction
    float acc[8][8];
    #pragma unroll
    for (int i = 0; i < 8; i++)
        #pragma unroll
        for (int j = 0; j < 8; j++) acc[i][j] = 0.f;

    // prologue: fill buffer 0
    {
        float4 a  = *(const float4*)(xg);
        float4 bv = *(const float4*)(wg);
        As[0][lc  ][lr] = a.x;  As[0][lc+1][lr] = a.y;  As[0][lc+2][lr] = a.z;  As[0][lc+3][lr] = a.w;
        Bs[0][lc  ][lr] = bv.x; Bs[0][lc+1][lr] = bv.y; Bs[0][lc+2][lr] = bv.z; Bs[0][lc+3][lr] = bv.w;
    }
    __syncthreads();

    int buf = 0;
    for (int k0 = 0; k0 < CC; k0 += 8) {
        float4 a, bv;
        bool more = (k0 + 8 < CC);
        if (more) {
            a  = *(const float4*)(xg + k0 + 8);
            bv = *(const float4*)(wg + k0 + 8);
        }
        #pragma unroll
        for (int kk = 0; kk < 8; kk++) {
            float4 a0 = *(const float4*)&As[buf][kk][ty*4];
            float4 a1 = *(const float4*)&As[buf][kk][64 + ty*4];
            float4 b0 = *(const float4*)&Bs[buf][kk][tx*4];
            float4 b1 = *(const float4*)&Bs[buf][kk][64 + tx*4];
            float ra[8] = {a0.x,a0.y,a0.z,a0.w,a1.x,a1.y,a1.z,a1.w};
            float rb[8] = {b0.x,b0.y,b0.z,b0.w,b1.x,b1.y,b1.z,b1.w};
            #pragma unroll
            for (int i = 0; i < 8; i++)
                #pragma unroll
                for (int j = 0; j < 8; j++)
                    acc[i][j] += ra[i] * rb[j];     // serial over k, strict order
        }
        if (more) {
            int nb = buf ^ 1;
            As[nb][lc  ][lr] = a.x;  As[nb][lc+1][lr] = a.y;  As[nb][lc+2][lr] = a.z;  As[nb][lc+3][lr] = a.w;
            Bs[nb][lc  ][lr] = bv.x; Bs[nb][lc+1][lr] = bv.y; Bs[nb][lc+2][lr] = bv.z; Bs[nb][lc+3][lr] = bv.w;
        }
        __syncthreads();
        buf ^= 1;
    }
    int b  = mBlk >> 12;          // 4096 rows per batch, mBlk multiple of 128
    int n0 = mBlk & 4095;
    #pragma unroll
    for (int j = 0; j < 8; j++) {
        int o = oBlk + ((j < 4) ? tx*4 + j : 64 + tx*4 + (j - 4));
        float bb = bias[o];
        float* dst = (o < CC) ? g_qn : g_kn;
        int oc = o & (CC - 1);
        size_t base = ((size_t)b*CC + oc) * NN + n0;
        #pragma unroll
        for (int g = 0; g < 2; g++) {
            int m0 = g*64 + ty*4;
            float4 v;
            v.x = __fadd_rn(acc[g*4+0][j], bb);
            v.y = __fadd_rn(acc[g*4+1][j], bb);
            v.z = __fadd_rn(acc[g*4+2][j], bb);
            v.w = __fadd_rn(acc[g*4+3][j], bb);
            *(float4*)(dst + base + m0) = v;
        }
    }
}

// ------------- 2) spatial gate logits (q & k merged): dwconv3x3 + BN + relu, dot pw_w -------------
// grid 2048: sel = bx>>10 (0=q, 1=k); per-path grid 1024 as before.
__global__ __launch_bounds__(256) void k_spatial(
    const float* __restrict__ dw_w_q, const float* __restrict__ dw_b_q,
    const float* __restrict__ bn_g_q, const float* __restrict__ bn_b_q,
    const float* __restrict__ pw_w_q,
    const float* __restrict__ dw_w_k, const float* __restrict__ dw_b_k,
    const float* __restrict__ bn_g_k, const float* __restrict__ bn_b_k,
    const float* __restrict__ pw_w_k)
{
    int bx = blockIdx.x;
    int sel = bx >> 10;
    int rest = bx & 1023;
    const float* inp  = sel ? g_kn : g_qn;
    const float* dw_w = sel ? dw_w_k : dw_w_q;
    const float* dw_b = sel ? dw_b_k : dw_b_q;
    const float* bn_g = sel ? bn_g_k : bn_g_q;
    const float* bn_b = sel ? bn_b_k : bn_b_q;
    const float* pw_w = sel ? pw_w_k : pw_w_q;
    double* s_raw     = sel ? g_skd : g_sqd;

    int cch  = rest & 7;
    int tile = (rest >> 3) & 15;
    int b    = rest >> 7;
    int t = threadIdx.x;
    int pos = tile*256 + t;
    int h = pos >> 6, w = pos & 63;
    const float bnc = (float)(1.0/sqrt(1.0 + 1e-5));
    double acc = 0.0;
    int c0 = cch * 64;
    for (int c = c0; c < c0 + 64; c++) {
        const float* p  = inp + ((size_t)b*CC + c) * NN;
        const float* wd = dw_w + c*9;
        float conv = 0.f;
        #pragma unroll
        for (int dy = -1; dy <= 1; dy++) {
            int hh = h + dy;
            if (hh < 0 || hh > 63) continue;
            #pragma unroll
            for (int dx = -1; dx <= 1; dx++) {
                int wp = w + dx;
                if (wp < 0 || wp > 63) continue;
                conv += p[hh*64 + wp] * wd[(dy+1)*3 + (dx+1)];
            }
        }
        float y = __fadd_rn(__fmul_rn(__fadd_rn(conv, dw_b[c]), __fmul_rn(bn_g[c], bnc)), bn_b[c]);
        y = fmaxf(y, 0.f);
        float prod = __fmul_rn(y, pw_w[c]);
        acc += (double)prod;
    }
    atomicAdd(&s_raw[b*NN + pos], acc);
}

// ------------- 2b) sigmoid over the gate logits (q & k merged) -------------
__global__ __launch_bounds__(512) void k_sig()
{
    int bx = blockIdx.x;
    int sel = bx >> 6;
    int i = (bx & 63) * 512 + threadIdx.x;
    const double* a = sel ? g_skd : g_sqd;
    float* o        = sel ? g_sk  : g_sq;
    o[i] = sigm((float)a[i]);
}

// ------------- 3) pooled = mean_hw( nchw * s ) (q & k merged): fp32 products, fp64 reduce -------------
__global__ __launch_bounds__(256) void k_pool()
{
    int bx = blockIdx.x;
    int sel = bx >> 12;
    int bc = bx & 4095;             // b*512 + c
    int b  = bc >> 9;
    const float* p  = (sel ? g_kn : g_qn) + (size_t)bc * NN;
    const float* sp = (sel ? g_sk : g_sq) + b*NN;
    float* pool     = sel ? g_pk : g_pq;
    int t = threadIdx.x;
    double sum = 0.0;
    for (int j = t; j < NN; j += 256) {
        float prod = __fmul_rn(p[j], sp[j]);
        sum += (double)prod;
    }
    __shared__ double red[256];
    red[t] = sum; __syncthreads();
    for (int st = 128; st > 0; st >>= 1) {
        if (t < st) red[t] += red[t + st];
        __syncthreads();
    }
    if (t == 0) pool[bc] = __fmul_rn((float)red[0], 1.f / NN);
}

// ------------- 4) channel gate (q & k merged): fp64 dot -------------
__global__ __launch_bounds__(512) void k_chgate(
    const float* __restrict__ wq, const float* __restrict__ wk)
{
    int bx = blockIdx.x;
    int sel = bx >> 3;
    int b = bx & 7;
    const float* w    = sel ? wk   : wq;
    const float* pool = sel ? g_pk : g_pq;
    float* tg         = sel ? g_tk : g_tq;
    int o = threadIdx.x;
    __shared__ float ps[CC];
    ps[o] = pool[b*CC + o];
    __syncthreads();
    const float* wr = w + (size_t)o * CC;
    double dot = 0.0;
    #pragma unroll 4
    for (int c = 0; c < CC; c += 4) {
        float4 wv = *(const float4*)(wr + c);
        dot += (double)wv.x*ps[c] + (double)wv.y*ps[c+1] + (double)wv.z*ps[c+2] + (double)wv.w*ps[c+3];
    }
    tg[b*CC + o] = sigm((float)dot);
}

// ------------- 5) gates + elu+1 + RoPE (q & k merged), coalesced: 32 n per warp -------------
// block 256 = 32 n_l x 8 i_half; each thread does 2 i's. grid = 2*8*16*128 = 32768.
__global__ __launch_bounds__(256) void k_rope(
    const float* __restrict__ cosT, const float* __restrict__ sinT)
{
    int bx = blockIdx.x;
    int sel  = bx >> 14;
    int rest = bx & 16383;
    int nc   = rest & 127;
    int head = (rest >> 7) & 15;
    int b    = rest >> 11;
    const float* inp = sel ? g_kn : g_qn;
    const float* s   = sel ? g_sk : g_sq;
    const float* tg  = sel ? g_tk : g_tq;
    float* outr      = sel ? g_kr : g_qr;

    int t = threadIdx.x;
    int n_l = t & 31;
    int ih  = t >> 5;               // 0..7
    int n = nc*32 + n_l;
    float sg = s[b*NN + n];
    __shared__ float tile[32][32];
    #pragma unroll
    for (int ii = 0; ii < 2; ii++) {
        int i  = ih*2 + ii;          // 0..15
        int ig = head*16 + i;
        int c0 = 2*ig;
        float v0 = __fmul_rn(__fmul_rn(inp[((size_t)b*CC + c0    )*NN + n], sg), tg[b*CC + c0]);
        float v1 = __fmul_rn(__fmul_rn(inp[((size_t)b*CC + c0 + 1)*NN + n], sg), tg[b*CC + c0 + 1]);
        v0 = (v0 > 0.f) ? __fadd_rn(v0, 1.f) : __fadd_rn(expm1f(v0), 1.f);   // elu(x)+1
        v1 = (v1 > 0.f) ? __fadd_rn(v1, 1.f) : __fadd_rn(expm1f(v1), 1.f);
        float cs = cosT[n*256 + ig], sn = sinT[n*256 + ig];
        tile[n_l][2*i    ] = __fsub_rn(__fmul_rn(cs, v0), __fmul_rn(sn, v1));
        tile[n_l][2*i + 1] = __fadd_rn(__fmul_rn(sn, v0), __fmul_rn(cs, v1));
    }
    __syncthreads();
    size_t base = (((size_t)b*HEADS + head)*NN + (size_t)nc*32) * HD;
    int row = t >> 3, col = (t & 7) * 4;
    *(float4*)(outr + base + row*HD + col) = *(const float4*)&tile[row][col];
}

// ------------- 6) k_mean over n : fp64 accumulation -------------
__global__ __launch_bounds__(256) void k_kmean(const float* __restrict__ kr, float* __restrict__ km)
{
    int bh = blockIdx.x;            // 0..127
    int t = threadIdx.x;
    int d = t & 31, ch = t >> 5;
    const float* p = kr + (size_t)bh * NN * HD;
    double sum = 0.0;
    int j0 = ch * 512;
    for (int j = j0; j < j0 + 512; j++)
        sum += (double)p[(size_t)j*HD + d];
    __shared__ double red[256];
    red[t] = sum; __syncthreads();
    if (t < 32) {
        double s2 = 0.0;
        #pragma unroll
        for (int k = 0; k < 8; k++) s2 += red[k*32 + d];
        km[bh*HD + d] = __fmul_rn((float)s2, 1.f / NN);
    }
}

// ------------- 7) kv = sum_n k_rope[n,d] * v[n,e] : fp32 -------------
__global__ __launch_bounds__(256) void k_kv(
    const float* __restrict__ kr, const float* __restrict__ x, float* __restrict__ kv)
{
    int bx = blockIdx.x;
    int nch = bx & 7;
    int bh  = bx >> 3;
    int b = bh >> 4, h = bh & 15;
    int t = threadIdx.x;
    int d  = t & 31;
    int e0 = (t >> 5) * 4;
    __shared__ float ks[64*32];
    __shared__ float vs[64*32];
    float a0 = 0.f, a1 = 0.f, a2 = 0.f, a3 = 0.f;
    for (int sub = 0; sub < 8; sub++) {
        int nbase = nch*512 + sub*64;
        const float4* src = (const float4*)(kr + ((size_t)bh*NN + nbase) * HD);
        ((float4*)ks)[t]       = src[t];
        ((float4*)ks)[t + 256] = src[t + 256];
        #pragma unroll
        for (int r = 0; r < 2; r++) {
            int id = t + r*256;
            int nn = id >> 3, e4 = (id & 7) * 4;
            float4 vv = *(const float4*)(x + ((size_t)b*NN + nbase + nn)*CC + h*HD + e4);
            *(float4*)&vs[nn*32 + e4] = vv;
        }
        __syncthreads();
        #pragma unroll 8
        for (int nn2 = 0; nn2 < 64; nn2++) {
            float kd = ks[nn2*32 + d];
            a0 += kd * vs[nn2*32 + e0];
            a1 += kd * vs[nn2*32 + e0 + 1];
            a2 += kd * vs[nn2*32 + e0 + 2];
            a3 += kd * vs[nn2*32 + e0 + 3];
        }
        __syncthreads();
    }
    float* dst = kv + ((size_t)bh*HD + d) * HD + e0;
    atomicAdd(dst + 0, a0); atomicAdd(dst + 1, a1);
    atomicAdd(dst + 2, a2); atomicAdd(dst + 3, a3);
}

// ------------- 8) epilogue: 4 n per block; z via fp64 warp tree; q.kv fp32 ascending; lepe fp32 -------------
// grid 8192 (= b*1024), block 512.
__global__ __launch_bounds__(512) void k_final(
    const float* __restrict__ x, const float* __restrict__ qr,
    const float* __restrict__ km, const float* __restrict__ kv,
    const float* __restrict__ lw, const float* __restrict__ lb,
    float* __restrict__ out)
{
    int bx = blockIdx.x;
    int b  = bx >> 10;
    int n0 = (bx & 1023) * 4;
    int h = n0 >> 6, w0 = n0 & 63;
    int c = threadIdx.x;
    int head = c >> 5, lane = c & 31;
    __shared__ float qs[4][CC];
    __shared__ float zs[4][HEADS];
    #pragma unroll
    for (int r = 0; r < 4; r++)
        qs[r][c] = qr[(((size_t)b*HEADS + head)*NN + n0 + r)*HD + lane];
    // per-thread lepe weights (only row c is ever used by this thread)
    float lw9[9];
    #pragma unroll
    for (int k = 0; k < 9; k++) lw9[k] = lw[c*9 + k];
    __syncthreads();
    // z-dot: one warp per head, fp64 product + fp64 xor-shuffle tree (exact to ~1e-16)
    {
        float kmv = km[((size_t)b*HEADS + head)*HD + lane];
        #pragma unroll
        for (int r = 0; r < 4; r++) {
            double dz = (double)qs[r][head*HD + lane] * (double)kmv;
            #pragma unroll
            for (int m = 16; m > 0; m >>= 1)
                dz += __shfl_xor_sync(0xffffffffu, dz, m);
            if (lane == 0) zs[r][head] = 1.f / __fadd_rn((float)dz, 1e-6f);
        }
    }
    __syncthreads();
    // kv column for this c (L1-resident; reused across the 4 n)
    const float* kvp = kv + ((size_t)b*HEADS + head) * HD * HD + lane;
    float kvf[HD];
    #pragma unroll
    for (int d2 = 0; d2 < HD; d2++) kvf[d2] = __fmul_rn(kvp[d2*HD], 1.f / NN);
    const float* xb = x + (size_t)b*NN*CC + c;
    #pragma unroll
    for (int r = 0; r < 4; r++) {
        // out-dot: fp32 ascending-d FMA chain (identical order to R14)
        float dd = 0.f;
        #pragma unroll
        for (int d2 = 0; d2 < HD; d2++) dd += qs[r][head*HD + d2] * kvf[d2];
        int n = n0 + r, w = w0 + r;
        float lep = lb[c];
        #pragma unroll
        for (int dy = -1; dy <= 1; dy++) {
            int hh = h + dy;
            if (hh < 0 || hh > 63) continue;
            #pragma unroll
            for (int dx = -1; dx <= 1; dx++) {
                int wp = w + dx;
                if (wp < 0 || wp > 63) continue;
                lep += xb[(size_t)(hh*64 + wp)*CC] * lw9[(dy+1)*3 + (dx+1)];
            }
        }
        out[((size_t)b*NN + n)*CC + c] = __fadd_rn(__fmul_rn(dd, zs[r][head]), lep);
    }
}

// ---------------- launch ----------------
extern "C" void kernel_launch(void* const* d_in, const int* in_sizes, int n_in,
                              void* d_out, int out_size)
{
    const float* x        = (const float*)d_in[0];
    const float* qk_w     = (const float*)d_in[1];
    const float* qk_b     = (const float*)d_in[2];
    const float* qsp_dw_w = (const float*)d_in[3];
    const float* qsp_dw_b = (const float*)d_in[4];
    const float* qsp_bn_g = (const float*)d_in[5];
    const float* qsp_bn_b = (const float*)d_in[6];
    const float* qsp_pw_w = (const float*)d_in[7];
    const float* qch_w    = (const float*)d_in[8];
    const float* ksp_dw_w = (const float*)d_in[9];
    const float* ksp_dw_b = (const float*)d_in[10];
    const float* ksp_bn_g = (const float*)d_in[11];
    const float* ksp_bn_b = (const float*)d_in[12];
    const float* ksp_pw_w = (const float*)d_in[13];
    const float* kch_w    = (const float*)d_in[14];
    const float* lepe_w   = (const float*)d_in[15];
    const float* lepe_b   = (const float*)d_in[16];
    const float* rope_cos = (const float*)d_in[17];
    const float* rope_sin = (const float*)d_in[18];

    float  *p_qr, *p_kr, *p_km, *p_kv;
    double *p_sqd, *p_skd;
    cudaGetSymbolAddress((void**)&p_qr, g_qr);
    cudaGetSymbolAddress((void**)&p_kr, g_kr);
    cudaGetSymbolAddress((void**)&p_sqd, g_sqd);
    cudaGetSymbolAddress((void**)&p_skd, g_skd);
    cudaGetSymbolAddress((void**)&p_km, g_km);
    cudaGetSymbolAddress((void**)&p_kv, g_kv);

    cudaMemsetAsync(p_sqd, 0, BB*NN*sizeof(double));
    cudaMemsetAsync(p_skd, 0, BB*NN*sizeof(double));
    cudaMemsetAsync(p_kv, 0, BB*HEADS*HD*HD*sizeof(float));

    dim3 gg(256, 8);
    k_gemm_qk<<<gg, 256>>>(x, qk_w, qk_b);

    k_spatial<<<2048, 256>>>(qsp_dw_w, qsp_dw_b, qsp_bn_g, qsp_bn_b, qsp_pw_w,
                             ksp_dw_w, ksp_dw_b, ksp_bn_g, ksp_bn_b, ksp_pw_w);
    k_sig<<<128, 512>>>();
    k_pool<<<8192, 256>>>();
    k_chgate<<<16, 512>>>(qch_w, kch_w);

    k_rope<<<32768, 256>>>(rope_cos, rope_sin);

    k_kmean<<<128, 256>>>(p_kr, p_km);
    k_kv<<<1024, 256>>>(p_kr, x, p_kv);

    k_final<<<8192, 512>>>(x, p_qr, p_km, p_kv, lepe_w, lepe_b, (float*)d_out);
}